// round 6
// baseline (speedup 1.0000x reference)
#include <cuda_runtime.h>

#define Nn 384
#define Dm 256
#define MARGIN 0.2f
#define ANCH 3
#define NBLK (Nn / ANCH)   // 128
#define NTHR 384
#define NWARP 12
#define JB 4

__device__ float4   en4[Nn * 64];   // normalized embeddings (float4 view)
__device__ float    g_psum[NBLK];
__device__ int      g_pcnt[NBLK];
__device__ unsigned g_ready;        // phase-A grid barrier counter
__device__ unsigned g_flag;        // last-block election counter

__global__ void __launch_bounds__(NTHR, 1)
k_fused(const float* __restrict__ e, const int* __restrict__ lab,
        float* __restrict__ out) {
    __shared__ float4 ea4[ANCH * 64];    // normalized anchor rows
    __shared__ float  Drow[ANCH][Nn];    // dots -> distances (in place)
    __shared__ int    slab[Nn];
    __shared__ float  pd[Nn];            // compacted positive distances
    __shared__ int    wcnt[NWARP];
    __shared__ float  rsum[NWARP];
    __shared__ int    rcnt[NWARP];
    __shared__ int    s_last;

    const int t = threadIdx.x, w = t >> 5, lane = t & 31;
    const int a0 = blockIdx.x * ANCH;

    if (t < Nn) slab[t] = lab[t];

    // ---- Phase A: normalize this block's 3 rows into en4 (warp per row) ----
    if (w < ANCH) {
        const float4* src = (const float4*)(e + (a0 + w) * Dm);
        float4 x0 = src[lane], x1 = src[lane + 32];
        float s = x0.x * x0.x;
        s = fmaf(x0.y, x0.y, s); s = fmaf(x0.z, x0.z, s); s = fmaf(x0.w, x0.w, s);
        s = fmaf(x1.x, x1.x, s); s = fmaf(x1.y, x1.y, s);
        s = fmaf(x1.z, x1.z, s); s = fmaf(x1.w, x1.w, s);
        #pragma unroll
        for (int o = 16; o > 0; o >>= 1) s += __shfl_xor_sync(0xffffffffu, s, o);
        float inv = rsqrtf(fmaxf(s, 1e-24f));
        x0.x *= inv; x0.y *= inv; x0.z *= inv; x0.w *= inv;
        x1.x *= inv; x1.y *= inv; x1.z *= inv; x1.w *= inv;
        en4[(a0 + w) * 64 + lane]      = x0;
        en4[(a0 + w) * 64 + lane + 32] = x1;
        ea4[w * 64 + lane]      = x0;
        ea4[w * 64 + lane + 32] = x1;
        __threadfence();
    }
    __syncthreads();

    // ---- Grid barrier: all 128 co-resident blocks finished phase A ----
    if (t == 0) {
        __threadfence();
        atomicAdd(&g_ready, 1u);
        while (atomicAdd(&g_ready, 0u) < (unsigned)NBLK) { }
        __threadfence();
    }
    __syncthreads();

    // ---- Phase 2: 8 lanes per j, 4 j's per warp, software-pipelined LDG ----
    const int jj = lane >> 3;            // which j within the group of 4
    const int kk = lane & 7;             // which k-slice (8 float4 per lane)

    float4 v[8];
    {
        const float4* __restrict__ row = en4 + (w * JB + jj) * 64;
        #pragma unroll
        for (int c = 0; c < 8; c++) v[c] = row[kk + 8 * c];
    }

    for (int jb = w * JB; jb < Nn; jb += NWARP * JB) {
        // prefetch next tile (wraps to row block 0 harmlessly on last iter)
        const int jbn = (jb + NWARP * JB < Nn) ? (jb + NWARP * JB) : 0;
        const float4* __restrict__ rown = en4 + (jbn + jj) * 64;
        float4 nv[8];
        #pragma unroll
        for (int c = 0; c < 8; c++) nv[c] = rown[kk + 8 * c];

        float c0 = 0.f, c1 = 0.f, c2 = 0.f;
        #pragma unroll
        for (int c = 0; c < 8; c++) {
            const int f = kk + 8 * c;
            float4 b0 = ea4[0 * 64 + f];
            float4 b1 = ea4[1 * 64 + f];
            float4 b2 = ea4[2 * 64 + f];
            c0 = fmaf(b0.x, v[c].x, c0); c0 = fmaf(b0.y, v[c].y, c0);
            c0 = fmaf(b0.z, v[c].z, c0); c0 = fmaf(b0.w, v[c].w, c0);
            c1 = fmaf(b1.x, v[c].x, c1); c1 = fmaf(b1.y, v[c].y, c1);
            c1 = fmaf(b1.z, v[c].z, c1); c1 = fmaf(b1.w, v[c].w, c1);
            c2 = fmaf(b2.x, v[c].x, c2); c2 = fmaf(b2.y, v[c].y, c2);
            c2 = fmaf(b2.z, v[c].z, c2); c2 = fmaf(b2.w, v[c].w, c2);
        }
        // reduce within 8-lane groups: 3 butterfly steps, 4 j's at once
        #pragma unroll
        for (int o = 1; o < 8; o <<= 1) {
            c0 += __shfl_xor_sync(0xffffffffu, c0, o);
            c1 += __shfl_xor_sync(0xffffffffu, c1, o);
            c2 += __shfl_xor_sync(0xffffffffu, c2, o);
        }
        if (kk == 0) {
            const int j = jb + jj;
            Drow[0][j] = c0;
            Drow[1][j] = c1;
            Drow[2][j] = c2;
        }
        #pragma unroll
        for (int c = 0; c < 8; c++) v[c] = nv[c];
    }
    __syncthreads();

    // ---- Parallel epilogue: dot -> distance, thread t = column j ----
    {
        #pragma unroll
        for (int aa = 0; aa < ANCH; aa++) {
            float d2 = 2.0f - 2.0f * Drow[aa][t];
            d2 = fmaxf(d2, 0.0f);
            Drow[aa][t] = (d2 > 0.0f) ? sqrtf(d2) : 0.0f;
        }
    }
    __syncthreads();

    // ---- Phase 3+4: per anchor, ballot-compaction of positives + negative scan ----
    float lsum = 0.0f;
    int   lcnt = 0;
    #pragma unroll
    for (int aa = 0; aa < ANCH; aa++) {
        const int a  = a0 + aa;
        const int la = slab[a];
        bool isp = (slab[t] == la) && (t != a);
        unsigned m = __ballot_sync(0xffffffffu, isp);
        if (lane == 0) wcnt[w] = __popc(m);
        __syncthreads();
        int off = 0, npos = 0;
        #pragma unroll
        for (int i = 0; i < NWARP; i++) {
            int c = wcnt[i];
            if (i < w) off += c;
            npos += c;
        }
        if (isp) pd[off + __popc(m & ((1u << lane) - 1u))] = Drow[aa][t];
        __syncthreads();

        if (slab[t] != la) {
            float dn = Drow[aa][t];
            for (int i = 0; i < npos; i++) {
                float tm = dn - pd[i];
                // semihard & loss>0  <=>  0 < tm < MARGIN (tm==MARGIN adds 0)
                if (tm > 0.0f && tm < MARGIN) { lsum += (MARGIN - tm); lcnt++; }
            }
        }
        __syncthreads();
    }

    // ---- Block reduction (fixed order, deterministic) ----
    #pragma unroll
    for (int o = 16; o > 0; o >>= 1) {
        lsum += __shfl_xor_sync(0xffffffffu, lsum, o);
        lcnt += __shfl_xor_sync(0xffffffffu, lcnt, o);
    }
    if (lane == 0) { rsum[w] = lsum; rcnt[w] = lcnt; }
    __syncthreads();
    if (t == 0) {
        float s = 0.0f; int c = 0;
        #pragma unroll
        for (int i = 0; i < NWARP; i++) { s += rsum[i]; c += rcnt[i]; }
        g_psum[blockIdx.x] = s;
        g_pcnt[blockIdx.x] = c;
        __threadfence();
        unsigned old = atomicAdd(&g_flag, 1u);
        s_last = (old == NBLK - 1) ? 1 : 0;
    }
    __syncthreads();

    // ---- Last block folds the 128 partials (deterministic order) ----
    if (s_last) {
        float s2 = (t < NBLK) ? g_psum[t] : 0.0f;
        int   c2 = (t < NBLK) ? g_pcnt[t] : 0;
        #pragma unroll
        for (int o = 16; o > 0; o >>= 1) {
            s2 += __shfl_xor_sync(0xffffffffu, s2, o);
            c2 += __shfl_xor_sync(0xffffffffu, c2, o);
        }
        if (lane == 0 && w < 4) { rsum[w] = s2; rcnt[w] = c2; }
        __syncthreads();
        if (t == 0) {
            float ts = rsum[0] + rsum[1] + rsum[2] + rsum[3];
            int   tc = rcnt[0] + rcnt[1] + rcnt[2] + rcnt[3];
            out[0] = (tc > 0) ? (ts / (float)tc) : 0.0f;
            g_flag  = 0;   // reset for next graph replay
            g_ready = 0;
        }
    }
}

extern "C" void kernel_launch(void* const* d_in, const int* in_sizes, int n_in,
                              void* d_out, int out_size) {
    const float* e   = (const float*)d_in[0];
    const int*   lab = (const int*)d_in[1];
    k_fused<<<NBLK, NTHR>>>(e, lab, (float*)d_out);
}

// round 7
// speedup vs baseline: 1.2000x; 1.2000x over previous
#include <cuda_runtime.h>

#define Nn 384
#define Dm 256
#define MARGIN 0.2f
#define ANCH 3
#define NBLK (Nn / ANCH)   // 128
#define NTHR 384
#define NWARP 12
#define JB 4

typedef unsigned long long u64;

__device__ float    g_psum[NBLK];
__device__ int      g_pcnt[NBLK];
__device__ unsigned g_flag;      // zero-init; last block resets to 0 each run

__device__ __forceinline__ u64 ffma2(u64 a, u64 b, u64 c) {
    u64 d;
    asm("fma.rn.f32x2 %0, %1, %2, %3;" : "=l"(d) : "l"(a), "l"(b), "l"(c));
    return d;
}
__device__ __forceinline__ float hadd2(u64 p) {
    float lo, hi;
    asm("mov.b64 {%0, %1}, %2;" : "=f"(lo), "=f"(hi) : "l"(p));
    return lo + hi;
}

__global__ void __launch_bounds__(NTHR, 1)
k_fused(const float* __restrict__ e, const int* __restrict__ lab,
        float* __restrict__ out) {
    __shared__ ulonglong2 ea[ANCH * 64];  // raw anchor rows (packed f32x2 pairs)
    __shared__ float  Drow[ANCH][Nn];     // raw dots -> distances (in place)
    __shared__ float  sssq[Nn];           // raw squared norms per j
    __shared__ int    slab[Nn];
    __shared__ float  pd[Nn];             // compacted positive distances
    __shared__ int    wcnt[NWARP];
    __shared__ float  rsum[NWARP];
    __shared__ int    rcnt[NWARP];
    __shared__ int    s_last;

    const int t = threadIdx.x, w = t >> 5, lane = t & 31;
    const int a0 = blockIdx.x * ANCH;

    if (t < Nn) slab[t] = lab[t];
    {
        const ulonglong2* src = (const ulonglong2*)(e + a0 * Dm);
        if (t < ANCH * 64) ea[t] = src[t];
    }
    __syncthreads();

    // ---- Phase 2: 8 lanes per j, 4 j's per warp, pipelined LDG, packed FMA ----
    const int jj = lane >> 3;            // which j within the group of 4
    const int kk = lane & 7;             // which k-slice (8x16B per lane)

    ulonglong2 v[8];
    {
        const ulonglong2* __restrict__ row = (const ulonglong2*)(e + (w * JB + jj) * Dm);
        #pragma unroll
        for (int c = 0; c < 8; c++) v[c] = row[kk + 8 * c];
    }

    for (int jb = w * JB; jb < Nn; jb += NWARP * JB) {
        // prefetch next tile (wraps to row block 0 harmlessly on last iter)
        const int jbn = (jb + NWARP * JB < Nn) ? (jb + NWARP * JB) : 0;
        const ulonglong2* __restrict__ rown = (const ulonglong2*)(e + (jbn + jj) * Dm);
        ulonglong2 nv[8];
        #pragma unroll
        for (int c = 0; c < 8; c++) nv[c] = rown[kk + 8 * c];

        u64 qp = 0ull, s0 = 0ull, s1 = 0ull, s2 = 0ull;
        #pragma unroll
        for (int c = 0; c < 8; c++) {
            const int f = kk + 8 * c;
            ulonglong2 b0 = ea[0 * 64 + f];
            ulonglong2 b1 = ea[1 * 64 + f];
            ulonglong2 b2 = ea[2 * 64 + f];
            ulonglong2 vv = v[c];
            qp = ffma2(vv.x, vv.x, qp); qp = ffma2(vv.y, vv.y, qp);
            s0 = ffma2(b0.x, vv.x, s0); s0 = ffma2(b0.y, vv.y, s0);
            s1 = ffma2(b1.x, vv.x, s1); s1 = ffma2(b1.y, vv.y, s1);
            s2 = ffma2(b2.x, vv.x, s2); s2 = ffma2(b2.y, vv.y, s2);
        }
        float q  = hadd2(qp);
        float c0 = hadd2(s0);
        float c1 = hadd2(s1);
        float c2 = hadd2(s2);
        // reduce within 8-lane groups: 3 butterfly steps, 4 j's at once
        #pragma unroll
        for (int o = 1; o < 8; o <<= 1) {
            q  += __shfl_xor_sync(0xffffffffu, q,  o);
            c0 += __shfl_xor_sync(0xffffffffu, c0, o);
            c1 += __shfl_xor_sync(0xffffffffu, c1, o);
            c2 += __shfl_xor_sync(0xffffffffu, c2, o);
        }
        if (kk == 0) {
            const int j = jb + jj;
            sssq[j]    = q;
            Drow[0][j] = c0;
            Drow[1][j] = c1;
            Drow[2][j] = c2;
        }
        #pragma unroll
        for (int c = 0; c < 8; c++) v[c] = nv[c];
    }
    __syncthreads();

    // ---- Parallel epilogue: raw dot -> distance, thread t = column j ----
    {
        float sj = rsqrtf(fmaxf(sssq[t], 1e-24f));
        #pragma unroll
        for (int aa = 0; aa < ANCH; aa++) {
            float sa = rsqrtf(fmaxf(sssq[a0 + aa], 1e-24f));
            float d2 = 2.0f - 2.0f * Drow[aa][t] * sa * sj;
            d2 = fmaxf(d2, 0.0f);
            Drow[aa][t] = (d2 > 0.0f) ? sqrtf(d2) : 0.0f;
        }
    }
    __syncthreads();

    // ---- Phase 3+4: per anchor, ballot-compaction of positives + negative scan ----
    float lsum = 0.0f;
    int   lcnt = 0;
    #pragma unroll
    for (int aa = 0; aa < ANCH; aa++) {
        const int a  = a0 + aa;
        const int la = slab[a];
        bool isp = (slab[t] == la) && (t != a);
        unsigned m = __ballot_sync(0xffffffffu, isp);
        if (lane == 0) wcnt[w] = __popc(m);
        __syncthreads();
        int off = 0, npos = 0;
        #pragma unroll
        for (int i = 0; i < NWARP; i++) {
            int c = wcnt[i];
            if (i < w) off += c;
            npos += c;
        }
        if (isp) pd[off + __popc(m & ((1u << lane) - 1u))] = Drow[aa][t];
        __syncthreads();

        if (slab[t] != la) {
            float dn = Drow[aa][t];
            for (int i = 0; i < npos; i++) {
                float tm = dn - pd[i];
                // semihard & loss>0  <=>  0 < tm < MARGIN (tm==MARGIN adds 0)
                if (tm > 0.0f && tm < MARGIN) { lsum += (MARGIN - tm); lcnt++; }
            }
        }
        __syncthreads();
    }

    // ---- Block reduction (fixed order, deterministic) ----
    #pragma unroll
    for (int o = 16; o > 0; o >>= 1) {
        lsum += __shfl_xor_sync(0xffffffffu, lsum, o);
        lcnt += __shfl_xor_sync(0xffffffffu, lcnt, o);
    }
    if (lane == 0) { rsum[w] = lsum; rcnt[w] = lcnt; }
    __syncthreads();
    if (t == 0) {
        float s = 0.0f; int c = 0;
        #pragma unroll
        for (int i = 0; i < NWARP; i++) { s += rsum[i]; c += rcnt[i]; }
        g_psum[blockIdx.x] = s;
        g_pcnt[blockIdx.x] = c;
        __threadfence();
        unsigned old = atomicAdd(&g_flag, 1u);
        s_last = (old == NBLK - 1) ? 1 : 0;
    }
    __syncthreads();

    // ---- Last block folds the 128 partials (deterministic order) ----
    if (s_last) {
        float s2 = (t < NBLK) ? g_psum[t] : 0.0f;
        int   c2 = (t < NBLK) ? g_pcnt[t] : 0;
        #pragma unroll
        for (int o = 16; o > 0; o >>= 1) {
            s2 += __shfl_xor_sync(0xffffffffu, s2, o);
            c2 += __shfl_xor_sync(0xffffffffu, c2, o);
        }
        if (lane == 0 && w < 4) { rsum[w] = s2; rcnt[w] = c2; }
        __syncthreads();
        if (t == 0) {
            float ts = rsum[0] + rsum[1] + rsum[2] + rsum[3];
            int   tc = rcnt[0] + rcnt[1] + rcnt[2] + rcnt[3];
            out[0] = (tc > 0) ? (ts / (float)tc) : 0.0f;
            g_flag = 0;   // reset for next graph replay
        }
    }
}

extern "C" void kernel_launch(void* const* d_in, const int* in_sizes, int n_in,
                              void* d_out, int out_size) {
    const float* e   = (const float*)d_in[0];
    const int*   lab = (const int*)d_in[1];
    k_fused<<<NBLK, NTHR>>>(e, lab, (float*)d_out);
}